// round 1
// baseline (speedup 1.0000x reference)
#include <cuda_runtime.h>
#include <cuda_bf16.h>
#include <cstdint>

// Problem constants
#define BB 32
#define SS 512
#define EE 300
#define EP 304          // padded K
#define HH 128
#define G4 512          // 4*H
#define NN 1024         // fused fwd+bwd gate width

// Scratch (device globals; allocation-free rule)
__device__ float g_X[(size_t)BB * SS * EP];        // padded embeddings [16384][304]
__device__ float g_W[(size_t)EP * NN];             // packed input weights W[k][n]
__device__ float g_bias[NN];
__device__ float g_G[(size_t)BB * SS * NN];        // gate preactivations [16384][1024]
__device__ float g_pooled[BB * 2 * HH];            // [b][dir*128+idx]

// ---------- f32x2 helpers ----------
__device__ __forceinline__ unsigned long long fma2(unsigned long long a,
                                                   unsigned long long b,
                                                   unsigned long long c) {
    unsigned long long d;
    asm("fma.rn.f32x2 %0, %1, %2, %3;" : "=l"(d) : "l"(a), "l"(b), "l"(c));
    return d;
}
__device__ __forceinline__ unsigned long long bcast2(float x) {
    unsigned long long d;
    asm("mov.b64 %0, {%1, %1};" : "=l"(d) : "f"(x));
    return d;
}
__device__ __forceinline__ float2 unpk(unsigned long long v) {
    float2 r;
    asm("mov.b64 {%0, %1}, %2;" : "=f"(r.x), "=f"(r.y) : "l"(v));
    return r;
}

__device__ __forceinline__ float fsigmoid(float x) {
    return 1.0f / (1.0f + __expf(-x));
}
__device__ __forceinline__ float ftanh(float x) {
    float ax = fabsf(x);
    float e = __expf(2.0f * ax);
    float t = 1.0f - 2.0f / (e + 1.0f);
    return copysignf(t, x);
}

// ---------- Kernel 1: pack input-projection weights + bias ----------
__global__ void pack_w_kernel(const float* __restrict__ Wih_f,
                              const float* __restrict__ Wih_b,
                              const float* __restrict__ b_f,
                              const float* __restrict__ b_b) {
    int idx = blockIdx.x * 256 + threadIdx.x;
    if (idx < EP * NN) {
        int k = idx >> 10;
        int n = idx & 1023;
        float v = 0.0f;
        if (k < EE) v = (n < G4) ? Wih_f[n * EE + k] : Wih_b[(n - G4) * EE + k];
        g_W[idx] = v;
    }
    if (idx < NN) g_bias[idx] = (idx < G4) ? b_f[idx] : b_b[idx - G4];
}

// ---------- Kernel 2: embeddings with dep-mean blend ----------
__global__ void embed_kernel(const int* __restrict__ word_ids,
                             const int* __restrict__ deps_ids,
                             const float* __restrict__ word_table,
                             const float* __restrict__ dep_table) {
    int bs = blockIdx.x;           // 0..16383
    int b = bs >> 9;
    int s = bs & 511;
    int wid = word_ids[b * (3 * SS) + SS + s];

    int ids[8];
    float cnt = 0.0f;
#pragma unroll
    for (int d = 0; d < 8; d++) {
        ids[d] = deps_ids[bs * 8 + d];
        if (ids[d] > 1) cnt += 1.0f;   // PAD=0, UNK=1
    }
    float inv = (cnt > 0.0f) ? 0.5f / cnt : 0.0f;
    float wscale = (cnt > 0.0f) ? 0.5f : 1.0f;

    for (int e = threadIdx.x; e < EP; e += 128) {
        float v = 0.0f;
        if (e < EE) {
            float w = word_table[(size_t)wid * EE + e];
            float sum = 0.0f;
#pragma unroll
            for (int d = 0; d < 8; d++) {
                if (ids[d] > 1) sum += dep_table[ids[d] * EE + e];
            }
            v = wscale * w + inv * sum;
        }
        g_X[(size_t)bs * EP + e] = v;
    }
}

// ---------- Kernel 3: GEMM G = X @ W + bias (M=16384, N=1024, K=304) ----------
__global__ void __launch_bounds__(256) gemm_kernel() {
    __shared__ float As[16][132];   // transposed A tile, padded
    __shared__ float Bs[16][64];

    int tid = threadIdx.x;
    int bm = blockIdx.x * 128;
    int bn = blockIdx.y * 64;
    int ty = tid >> 4, tx = tid & 15;     // compute layout: rows ty*8..+8, cols tx*4..+4
    int ar = tid >> 2, ac = (tid & 3) << 2;  // load layout

    unsigned long long acc[4][4];
#pragma unroll
    for (int q = 0; q < 4; q++)
#pragma unroll
        for (int n = 0; n < 4; n++) acc[q][n] = 0ull;

    for (int k0 = 0; k0 < EP; k0 += 16) {
#pragma unroll
        for (int rr = 0; rr < 2; rr++) {
            float4 a = *(const float4*)(g_X + (size_t)(bm + ar + rr * 64) * EP + k0 + ac);
            As[ac + 0][ar + rr * 64] = a.x;
            As[ac + 1][ar + rr * 64] = a.y;
            As[ac + 2][ar + rr * 64] = a.z;
            As[ac + 3][ar + rr * 64] = a.w;
        }
        *(float4*)&Bs[ty][tx * 4] =
            *(const float4*)(g_W + (size_t)(k0 + ty) * NN + bn + tx * 4);
        __syncthreads();

#pragma unroll
        for (int kk = 0; kk < 16; kk++) {
            const unsigned long long* ap = (const unsigned long long*)&As[kk][ty * 8];
            unsigned long long a0 = ap[0], a1 = ap[1], a2 = ap[2], a3 = ap[3];
            float4 bq = *(const float4*)&Bs[kk][tx * 4];
            unsigned long long b0 = bcast2(bq.x), b1 = bcast2(bq.y),
                               b2 = bcast2(bq.z), b3 = bcast2(bq.w);
            acc[0][0] = fma2(a0, b0, acc[0][0]); acc[0][1] = fma2(a0, b1, acc[0][1]);
            acc[0][2] = fma2(a0, b2, acc[0][2]); acc[0][3] = fma2(a0, b3, acc[0][3]);
            acc[1][0] = fma2(a1, b0, acc[1][0]); acc[1][1] = fma2(a1, b1, acc[1][1]);
            acc[1][2] = fma2(a1, b2, acc[1][2]); acc[1][3] = fma2(a1, b3, acc[1][3]);
            acc[2][0] = fma2(a2, b0, acc[2][0]); acc[2][1] = fma2(a2, b1, acc[2][1]);
            acc[2][2] = fma2(a2, b2, acc[2][2]); acc[2][3] = fma2(a2, b3, acc[2][3]);
            acc[3][0] = fma2(a3, b0, acc[3][0]); acc[3][1] = fma2(a3, b1, acc[3][1]);
            acc[3][2] = fma2(a3, b2, acc[3][2]); acc[3][3] = fma2(a3, b3, acc[3][3]);
        }
        __syncthreads();
    }

    float bb0 = g_bias[bn + tx * 4 + 0];
    float bb1 = g_bias[bn + tx * 4 + 1];
    float bb2 = g_bias[bn + tx * 4 + 2];
    float bb3 = g_bias[bn + tx * 4 + 3];
#pragma unroll
    for (int q = 0; q < 4; q++) {
        float2 v0 = unpk(acc[q][0]), v1 = unpk(acc[q][1]);
        float2 v2 = unpk(acc[q][2]), v3 = unpk(acc[q][3]);
        int row0 = bm + ty * 8 + q * 2;
        *(float4*)(g_G + (size_t)row0 * NN + bn + tx * 4) =
            make_float4(v0.x + bb0, v1.x + bb1, v2.x + bb2, v3.x + bb3);
        *(float4*)(g_G + (size_t)(row0 + 1) * NN + bn + tx * 4) =
            make_float4(v0.y + bb0, v1.y + bb1, v2.y + bb2, v3.y + bb3);
    }
}

// ---------- Kernel 4: LSTM scan (one CTA per (batch, dir)) ----------
// 512 threads: thread j owns gate row j. 96 K-values in regs (48 f32x2),
// 32 K-values in transposed packed SMEM. h broadcast from SMEM via LDS.128.
#define SCAN_SMEM (2560 + 16 * 512 * 8)

__global__ void __launch_bounds__(512, 1)
lstm_scan_kernel(const float* __restrict__ Whh_f, const float* __restrict__ Whh_b) {
    extern __shared__ unsigned char sm[];
    float* h_sh = (float*)sm;                                   // 128 floats
    float* gs = (float*)(sm + 512);                             // 512 floats
    unsigned long long* wsp = (unsigned long long*)(sm + 2560); // [16][512]

    int j = threadIdx.x;
    int b = blockIdx.x;
    int dir = blockIdx.y;
    const float* Whh = dir ? Whh_b : Whh_f;

    const unsigned long long* wrow = (const unsigned long long*)(Whh + j * HH);
    unsigned long long wreg[48];
#pragma unroll
    for (int m = 0; m < 48; m++) wreg[m] = wrow[m];
#pragma unroll
    for (int m = 0; m < 16; m++) wsp[m * 512 + j] = wrow[48 + m];

    if (j < HH) h_sh[j] = 0.0f;
    float c = 0.0f, hmax = -1e30f;

    const float* gp = dir ? (g_G + ((size_t)(b * SS + SS - 1)) * NN + G4 + j)
                          : (g_G + ((size_t)(b * SS)) * NN + j);
    int stepoff = dir ? -(int)NN : (int)NN;

    __syncthreads();

    for (int t = 0; t < SS; t++) {
        float gpre = __ldg(gp);
        gp += stepoff;

        const ulonglong2* hq4 = (const ulonglong2*)h_sh;
        unsigned long long acc0 = 0ull, acc1 = 0ull;
#pragma unroll
        for (int m2 = 0; m2 < 24; m2++) {
            ulonglong2 hq = hq4[m2];
            acc0 = fma2(wreg[2 * m2 + 0], hq.x, acc0);
            acc1 = fma2(wreg[2 * m2 + 1], hq.y, acc1);
        }
#pragma unroll
        for (int m2 = 0; m2 < 8; m2++) {
            ulonglong2 hq = hq4[24 + m2];
            acc0 = fma2(wsp[(2 * m2 + 0) * 512 + j], hq.x, acc0);
            acc1 = fma2(wsp[(2 * m2 + 1) * 512 + j], hq.y, acc1);
        }
        float2 s0 = unpk(acc0), s1 = unpk(acc1);
        gs[j] = gpre + s0.x + s0.y + s1.x + s1.y;
        __syncthreads();

        if (j < HH) {
            float pi = gs[j], pf = gs[HH + j], pg = gs[2 * HH + j], po = gs[3 * HH + j];
            float ig = fsigmoid(pi);
            float fg = fsigmoid(pf);
            float og = fsigmoid(po);
            float gg = ftanh(pg);
            c = fg * c + ig * gg;
            float hh = og * ftanh(c);
            h_sh[j] = hh;
            hmax = fmaxf(hmax, hh);
        }
        __syncthreads();
    }

    if (j < HH) g_pooled[b * 256 + dir * HH + j] = hmax;
}

// ---------- Kernel 5: classifier ----------
__global__ void cls_kernel(const float* __restrict__ W_cls,
                           const float* __restrict__ b_cls,
                           float* __restrict__ out) {
    int t = threadIdx.x;
    if (t >= BB * 5) return;
    int b = t / 5, l = t % 5;
    float s = b_cls[l];
#pragma unroll 8
    for (int k = 0; k < 256; k++) s += g_pooled[b * 256 + k] * W_cls[l * 256 + k];
    out[b * 5 + l] = s;
}

// ---------- launch ----------
extern "C" void kernel_launch(void* const* d_in, const int* in_sizes, int n_in,
                              void* d_out, int out_size) {
    const int*   word_ids   = (const int*)d_in[0];
    const int*   deps_ids   = (const int*)d_in[1];
    const float* word_table = (const float*)d_in[2];
    const float* dep_table  = (const float*)d_in[3];
    const float* Wih_f      = (const float*)d_in[4];
    const float* Whh_f      = (const float*)d_in[5];
    const float* b_f        = (const float*)d_in[6];
    const float* Wih_b      = (const float*)d_in[7];
    const float* Whh_b      = (const float*)d_in[8];
    const float* b_b        = (const float*)d_in[9];
    const float* W_cls      = (const float*)d_in[10];
    const float* b_cls      = (const float*)d_in[11];
    float* out = (float*)d_out;

    cudaFuncSetAttribute(lstm_scan_kernel,
                         cudaFuncAttributeMaxDynamicSharedMemorySize, SCAN_SMEM);

    pack_w_kernel<<<(EP * NN + 255) / 256, 256>>>(Wih_f, Wih_b, b_f, b_b);
    embed_kernel<<<BB * SS, 128>>>(word_ids, deps_ids, word_table, dep_table);
    gemm_kernel<<<dim3((BB * SS) / 128, NN / 64), 256>>>();
    lstm_scan_kernel<<<dim3(BB, 2), 512, SCAN_SMEM>>>(Whh_f, Whh_b);
    cls_kernel<<<1, 256>>>(W_cls, b_cls, out);
}